// round 8
// baseline (speedup 1.0000x reference)
#include <cuda_runtime.h>
#include <cstdint>

// Problem constants
#define B_NODES 100000
#define U_NODES 50000
#define NTOT    150000
#define F_DIM   512
#define D_DIM   128
#define K_NEIGH 10
#define KOUT    1152

#define SMEM_SWIZZLE_128B(byte_offset) ((byte_offset) ^ (((byte_offset) >> 3) & 0x70))

// ---------------------------------------------------------------------------
// Warp-level tensor-core primitives (sm_80+ features; safe for compute_103)
// ---------------------------------------------------------------------------
__device__ __forceinline__ uint32_t smem_u32(const void* p) {
    uint32_t a;
    asm("{ .reg .u64 t; cvta.to.shared.u64 t, %1; cvt.u32.u64 %0, t; }" : "=r"(a) : "l"(p));
    return a;
}

__device__ __forceinline__ void ldm_x4(uint32_t* r, uint32_t addr) {
    asm volatile("ldmatrix.sync.aligned.m8n8.x4.shared.b16 {%0,%1,%2,%3}, [%4];"
        : "=r"(r[0]), "=r"(r[1]), "=r"(r[2]), "=r"(r[3]) : "r"(addr));
}

// m16n8k8 tf32 MMA, fp32 accumulate
__device__ __forceinline__ void mma_tf32(float* c, const uint32_t* a,
                                         uint32_t b0, uint32_t b1) {
    asm volatile("mma.sync.aligned.m16n8k8.row.col.f32.tf32.tf32.f32 "
        "{%0,%1,%2,%3}, {%4,%5,%6,%7}, {%8,%9}, {%0,%1,%2,%3};"
        : "+f"(c[0]), "+f"(c[1]), "+f"(c[2]), "+f"(c[3])
        : "r"(a[0]), "r"(a[1]), "r"(a[2]), "r"(a[3]), "r"(b0), "r"(b1));
}

__device__ __forceinline__ uint32_t to_tf32(float x) {
    uint32_t r;
    asm("cvt.rna.tf32.f32 %0, %1;" : "=r"(r) : "f"(x));
    return r;
}

__device__ __forceinline__ void cp_async16(uint32_t dst, const void* src) {
    asm volatile("cp.async.cg.shared.global [%0], [%1], 16;" :: "r"(dst), "l"(src) : "memory");
}
#define CP_ASYNC_COMMIT() asm volatile("cp.async.commit_group;" ::: "memory")
#define CP_ASYNC_WAIT0()  asm volatile("cp.async.wait_group 0;" ::: "memory")

#define STS128(a0, a1, a2, a3, addr) \
    asm volatile("st.shared.v4.b32 [%0], {%1, %2, %3, %4};" \
        :: "r"(addr), "r"(a0), "r"(a1), "r"(a2), "r"(a3) : "memory")

// ---------------------------------------------------------------------------
// Device-global scratch (referenced ONLY from device code)
// ---------------------------------------------------------------------------
__device__ __align__(16) float g_h[(size_t)NTOT * D_DIM];
__device__ float g_s[NTOT];
__device__ __align__(16) float g_hprime[(size_t)B_NODES * D_DIM];
// tf32-rounded, transposed weights: [N=128][K] f32 (mma col-major B layout)
__device__ __align__(16) float g_WT1[(size_t)D_DIM * F_DIM];
__device__ __align__(16) float g_WT2[(size_t)D_DIM * KOUT];

// ---------------------------------------------------------------------------
// Weight transpose + tf32 rounding: src [K][128] fp32 -> dstT [128][K]
// ---------------------------------------------------------------------------
template <int WHICH>   // 1 = W (K=512), 2 = Wd (K=1152)
__global__ void convertW_kernel(const float* __restrict__ src)
{
    constexpr int K = (WHICH == 1) ? F_DIM : KOUT;
    float* dstT = (WHICH == 1) ? g_WT1 : g_WT2;

    int idx = blockIdx.x * blockDim.x + threadIdx.x;
    if (idx >= K * D_DIM) return;
    int k = idx >> 7, n = idx & 127;
    uint32_t t = to_tf32(src[idx]);
    dstT[(size_t)n * K + k] = __uint_as_float(t);
}

// ---------------------------------------------------------------------------
// Tensor-core GEMM, tf32 m16n8k8, 256x128 CTA tile, BK=32, 2-stage pipeline.
// 8 warps: 4(M) x 2(N), warp tile 64x64.
// Dynamic smem: 2 stages x (A 32KB + B 16KB) = 96KB (+1KB align). 1 CTA/SM.
// SMEM row = 32 f32 = 128 B, SW128-swizzled.
// MODE 1: A=[fb;fn] K=512 -> g_h.   MODE 2: A=[fb|h'|nf] K=1152 -> relu -> out.
// ---------------------------------------------------------------------------
template <int MODE>
__global__ void __launch_bounds__(256, 1)
gemm_mma_kernel(const float* __restrict__ fb, const float* __restrict__ fn,
                const float* __restrict__ nf, float* __restrict__ outp)
{
    constexpr int KTOT   = (MODE == 1) ? F_DIM : KOUT;
    constexpr int NCHUNK = KTOT / 32;
    constexpr int MROWS  = (MODE == 1) ? NTOT : B_NODES;

    extern __shared__ char dsm[];
    const uint32_t ab = (smem_u32(dsm) + 1023u) & ~1023u;

    const int tid = threadIdx.x;
    const int lane = tid & 31;
    const int wm = (tid >> 5) & 3;       // 0..3  (M groups of 64 rows)
    const int wn = (tid >> 5) >> 2;      // 0..1  (N groups of 64 cols)
    const int rowBase = blockIdx.x * 256;

    const float* BT = (MODE == 1) ? g_WT1 : g_WT2;

    float acc[4][8][4];
    #pragma unroll
    for (int i = 0; i < 4; ++i)
        #pragma unroll
        for (int j = 0; j < 8; ++j)
            #pragma unroll
            for (int q = 0; q < 4; ++q) acc[i][j][q] = 0.f;

    const int lr = lane & 7;
    const int lg = lane >> 3;

    // per-thread A staging: 4 idx-iterations x 8 floats (256 rows x 32 f32)
    float4 sa0[4], sa1[4];

    auto aSrc = [&](int grow, int k0c) -> const float* {
        if (MODE == 1) {
            return (grow < B_NODES) ? fb + (size_t)grow * F_DIM + k0c
                                    : fn + (size_t)(grow - B_NODES) * F_DIM + k0c;
        } else {
            if (k0c < 512)      return fb + (size_t)grow * F_DIM + k0c;
            else if (k0c < 640) return g_hprime + (size_t)grow * D_DIM + (k0c - 512);
            else                return nf + (size_t)grow * F_DIM + (k0c - 640);
        }
    };

    // Issue phase: LDG A into regs, cp.async B (tf32 f32) into stage smem.
    auto issueLoads = [&](int c, uint32_t stageB) {
        const int k0c = c * 32;
        #pragma unroll
        for (int i = 0; i < 4; ++i) {
            int idx = tid + i * 256;           // 0..1023
            int row = idx >> 2, seg = idx & 3; // 256 rows x 4 segs of 8 f32
            int grow = rowBase + row;
            sa0[i] = make_float4(0.f, 0.f, 0.f, 0.f);
            sa1[i] = sa0[i];
            if (grow < MROWS) {
                const float* src = aSrc(grow, k0c);
                sa0[i] = *(const float4*)(src + seg * 8);
                sa1[i] = *(const float4*)(src + seg * 8 + 4);
            }
        }
        #pragma unroll
        for (int i = 0; i < 4; ++i) {
            int idx = tid + i * 256;            // 0..1023
            int row = idx >> 3, seg = idx & 7;  // 128 rows x 8 segs of 16B
            uint32_t off = SMEM_SWIZZLE_128B((uint32_t)(row * 128 + seg * 16));
            cp_async16(stageB + off, BT + (size_t)row * KTOT + k0c + seg * 4);
        }
        CP_ASYNC_COMMIT();
    };

    // Commit phase: tf32-round staged A, store to smem; drain B cp.async.
    auto commitLoads = [&](uint32_t stageA) {
        #pragma unroll
        for (int i = 0; i < 4; ++i) {
            int idx = tid + i * 256;
            int row = idx >> 2, seg = idx & 3;
            uint32_t w[8];
            w[0] = to_tf32(sa0[i].x); w[1] = to_tf32(sa0[i].y);
            w[2] = to_tf32(sa0[i].z); w[3] = to_tf32(sa0[i].w);
            w[4] = to_tf32(sa1[i].x); w[5] = to_tf32(sa1[i].y);
            w[6] = to_tf32(sa1[i].z); w[7] = to_tf32(sa1[i].w);
            uint32_t off0 = SMEM_SWIZZLE_128B((uint32_t)(row * 128 + seg * 32));
            uint32_t off1 = SMEM_SWIZZLE_128B((uint32_t)(row * 128 + seg * 32 + 16));
            STS128(w[0], w[1], w[2], w[3], stageA + off0);
            STS128(w[4], w[5], w[6], w[7], stageA + off1);
        }
        CP_ASYNC_WAIT0();
    };

    // Compute one chunk: 4 k8 steps, warp tile 64x64.
    auto computeChunk = [&](uint32_t stageA, uint32_t stageB) {
        #pragma unroll
        for (int s = 0; s < 4; ++s) {
            const int kb = s * 32 + (lg >> 1) * 16;
            uint32_t af[4][4];
            #pragma unroll
            for (int i = 0; i < 4; ++i) {
                int row = wm * 64 + i * 16 + lr + (lg & 1) * 8;
                ldm_x4(af[i], stageA + SMEM_SWIZZLE_128B((uint32_t)(row * 128 + kb)));
            }
            uint32_t bfr[4][4];
            #pragma unroll
            for (int j = 0; j < 4; ++j) {
                int row = wn * 64 + j * 16 + lr + (lg & 1) * 8;
                ldm_x4(bfr[j], stageB + SMEM_SWIZZLE_128B((uint32_t)(row * 128 + kb)));
            }
            #pragma unroll
            for (int i = 0; i < 4; ++i)
                #pragma unroll
                for (int j = 0; j < 4; ++j) {
                    mma_tf32(acc[i][2 * j],     af[i], bfr[j][0], bfr[j][2]);
                    mma_tf32(acc[i][2 * j + 1], af[i], bfr[j][1], bfr[j][3]);
                }
        }
    };

    auto stA = [&](int s) { return ab + (uint32_t)s * 49152u; };
    auto stB = [&](int s) { return ab + (uint32_t)s * 49152u + 32768u; };

    // ---- prologue ----
    issueLoads(0, stB(0));
    commitLoads(stA(0));
    __syncthreads();

    // ---- main pipeline ----
    for (int c = 0; c < NCHUNK; ++c) {
        const int cur = c & 1, nxt = (c + 1) & 1;
        if (c + 1 < NCHUNK) issueLoads(c + 1, stB(nxt));
        computeChunk(stA(cur), stB(cur));
        if (c + 1 < NCHUNK) commitLoads(stA(nxt));
        __syncthreads();
    }

    // ---- epilogue ----
    float* dst = (MODE == 1) ? (float*)g_h : outp;
    const int qm = lane >> 2;
    const int qn = (lane & 3) * 2;
    #pragma unroll
    for (int i = 0; i < 4; ++i) {
        #pragma unroll
        for (int j = 0; j < 8; ++j) {
            int m0 = rowBase + wm * 64 + i * 16;
            int n  = wn * 64 + j * 8 + qn;
            float c0 = acc[i][j][0], c1 = acc[i][j][1];
            float c2 = acc[i][j][2], c3 = acc[i][j][3];
            if (MODE == 2) {
                c0 = fmaxf(c0, 0.f); c1 = fmaxf(c1, 0.f);
                c2 = fmaxf(c2, 0.f); c3 = fmaxf(c3, 0.f);
            }
            int r0 = m0 + qm, r1 = m0 + 8 + qm;
            if (r0 < MROWS) *(float2*)(dst + (size_t)r0 * D_DIM + n) = make_float2(c0, c1);
            if (r1 < MROWS) *(float2*)(dst + (size_t)r1 * D_DIM + n) = make_float2(c2, c3);
        }
    }
}

// ---------------------------------------------------------------------------
// s[r] = g_h[r,:] . (a[0:128] if r<B else a[128:256])
// ---------------------------------------------------------------------------
__global__ void __launch_bounds__(256) s_kernel(const float* __restrict__ avec)
{
    int gwarp = (blockIdx.x * blockDim.x + threadIdx.x) >> 5;
    int lane = threadIdx.x & 31;
    if (gwarp >= NTOT) return;
    const float* av = (gwarp < B_NODES) ? avec : avec + D_DIM;
    const float* hr = g_h + (size_t)gwarp * D_DIM;
    float sum = 0.f;
    #pragma unroll
    for (int i = 0; i < 4; ++i) {
        int c = lane + i * 32;
        sum += hr[c] * av[c];
    }
    #pragma unroll
    for (int off = 16; off > 0; off >>= 1)
        sum += __shfl_down_sync(0xffffffffu, sum, off);
    if (lane == 0) g_s[gwarp] = sum;
}

// ---------------------------------------------------------------------------
// Aggregation: one block per batch node; thread t owns feature column t.
// ---------------------------------------------------------------------------
__global__ void __launch_bounds__(128) agg_kernel(const int* __restrict__ edge_dst)
{
    const int i = blockIdx.x;
    const int t = threadIdx.x;
    __shared__ float w[K_NEIGH];
    __shared__ int   jj[K_NEIGH];
    if (t < K_NEIGH) {
        int j = edge_dst[(size_t)i * K_NEIGH + t];
        float sc = g_s[i] + g_s[B_NODES + j];
        float lr = sc > 0.f ? sc : 0.2f * sc;
        w[t]  = expf(-lr);
        jj[t] = j;
    }
    __syncthreads();
    float tot = 0.f, acc = 0.f;
    #pragma unroll
    for (int k = 0; k < K_NEIGH; ++k) {
        float wk = w[k];
        tot += wk;
        acc += wk * g_h[(size_t)(B_NODES + jj[k]) * D_DIM + t];
    }
    float v = acc / tot;
    if (!isfinite(v)) v = 0.f;
    g_hprime[(size_t)i * D_DIM + t] = v;
}

// ---------------------------------------------------------------------------
// Launch
// Inputs: 0=feats_batch 1=feats_neigh 2=neigh_feats 3=W 4=a 5=Wd 6=edge_src 7=edge_dst
// ---------------------------------------------------------------------------
extern "C" void kernel_launch(void* const* d_in, const int* in_sizes, int n_in,
                              void* d_out, int out_size)
{
    const float* fb   = (const float*)d_in[0];
    const float* fn   = (const float*)d_in[1];
    const float* nf   = (const float*)d_in[2];
    const float* W    = (const float*)d_in[3];
    const float* avec = (const float*)d_in[4];
    const float* Wd   = (const float*)d_in[5];
    const int* edge_dst = (const int*)d_in[7];
    float* out = (float*)d_out;
    (void)in_sizes; (void)n_in; (void)out_size;

    const int SMEM_BYTES = 99328;  // 2 x 48KB stages + 1KB align slack
    cudaFuncSetAttribute(gemm_mma_kernel<1>, cudaFuncAttributeMaxDynamicSharedMemorySize, SMEM_BYTES);
    cudaFuncSetAttribute(gemm_mma_kernel<2>, cudaFuncAttributeMaxDynamicSharedMemorySize, SMEM_BYTES);

    // 0) tf32-round + transpose weights [N][K]
    convertW_kernel<1><<<(F_DIM * D_DIM + 255) / 256, 256>>>(W);
    convertW_kernel<2><<<(KOUT * D_DIM + 255) / 256, 256>>>(Wd);

    // 1) h = [fb; fn] @ W
    gemm_mma_kernel<1><<<(NTOT + 255) / 256, 256, SMEM_BYTES>>>(fb, fn, nullptr, nullptr);

    // 2) per-row attention scalars
    s_kernel<<<(NTOT * 32 + 255) / 256, 256>>>(avec);

    // 3) per-node weighted aggregation
    agg_kernel<<<B_NODES, 128>>>(edge_dst);

    // 4) out = relu([fb | h' | nf] @ Wd)
    gemm_mma_kernel<2><<<(B_NODES + 255) / 256, 256, SMEM_BYTES>>>(fb, nullptr, nf, out);
}

// round 9
// speedup vs baseline: 1.5314x; 1.5314x over previous
#include <cuda_runtime.h>
#include <cuda_fp16.h>
#include <cstdint>

// Problem constants
#define B_NODES 100000
#define U_NODES 50000
#define NTOT    150000
#define F_DIM   512
#define D_DIM   128
#define K_NEIGH 10
#define KOUT    1152

#define SMEM_SWIZZLE_128B(byte_offset) ((byte_offset) ^ (((byte_offset) >> 3) & 0x70))

// ---------------------------------------------------------------------------
// Warp-level tensor-core primitives (sm_80+ features; safe for compute_103)
// ---------------------------------------------------------------------------
__device__ __forceinline__ uint32_t smem_u32(const void* p) {
    uint32_t a;
    asm("{ .reg .u64 t; cvta.to.shared.u64 t, %1; cvt.u32.u64 %0, t; }" : "=r"(a) : "l"(p));
    return a;
}

__device__ __forceinline__ void ldm_x4(uint32_t* r, uint32_t addr) {
    asm volatile("ldmatrix.sync.aligned.m8n8.x4.shared.b16 {%0,%1,%2,%3}, [%4];"
        : "=r"(r[0]), "=r"(r[1]), "=r"(r[2]), "=r"(r[3]) : "r"(addr));
}

// m16n8k16 fp16 MMA, fp32 accumulate
__device__ __forceinline__ void mma_f16(float* c, const uint32_t* a,
                                        uint32_t b0, uint32_t b1) {
    asm volatile("mma.sync.aligned.m16n8k16.row.col.f32.f16.f16.f32 "
        "{%0,%1,%2,%3}, {%4,%5,%6,%7}, {%8,%9}, {%0,%1,%2,%3};"
        : "+f"(c[0]), "+f"(c[1]), "+f"(c[2]), "+f"(c[3])
        : "r"(a[0]), "r"(a[1]), "r"(a[2]), "r"(a[3]), "r"(b0), "r"(b1));
}

__device__ __forceinline__ uint32_t pack_h2(float x, float y) {
    __half2 h = __float22half2_rn(make_float2(x, y));
    return *reinterpret_cast<uint32_t*>(&h);
}

__device__ __forceinline__ void cp_async16(uint32_t dst, const void* src) {
    asm volatile("cp.async.cg.shared.global [%0], [%1], 16;" :: "r"(dst), "l"(src) : "memory");
}
#define CP_ASYNC_COMMIT() asm volatile("cp.async.commit_group;" ::: "memory")
#define CP_ASYNC_WAIT0()  asm volatile("cp.async.wait_group 0;" ::: "memory")

#define STS128(a0, a1, a2, a3, addr) \
    asm volatile("st.shared.v4.b32 [%0], {%1, %2, %3, %4};" \
        :: "r"(addr), "r"(a0), "r"(a1), "r"(a2), "r"(a3) : "memory")

// ---------------------------------------------------------------------------
// Device-global scratch (referenced ONLY from device code)
// ---------------------------------------------------------------------------
__device__ __align__(16) float g_h[(size_t)NTOT * D_DIM];
__device__ float g_s[NTOT];
__device__ __align__(16) float g_hprime[(size_t)B_NODES * D_DIM];
// fp16 transposed weights: [N=128][K] (mma col-major B layout)
__device__ __align__(16) __half g_W16_1[(size_t)D_DIM * F_DIM];
__device__ __align__(16) __half g_W16_2[(size_t)D_DIM * KOUT];

// ---------------------------------------------------------------------------
// Weight transpose + fp16 rounding: src [K][128] fp32 -> dstT [128][K] fp16
// ---------------------------------------------------------------------------
template <int WHICH>   // 1 = W (K=512), 2 = Wd (K=1152)
__global__ void convertW_kernel(const float* __restrict__ src)
{
    constexpr int K = (WHICH == 1) ? F_DIM : KOUT;
    __half* dstT = (WHICH == 1) ? g_W16_1 : g_W16_2;

    int idx = blockIdx.x * blockDim.x + threadIdx.x;
    if (idx >= K * D_DIM) return;
    int k = idx >> 7, n = idx & 127;
    dstT[(size_t)n * K + k] = __float2half_rn(src[idx]);
}

// ---------------------------------------------------------------------------
// Tensor-core GEMM, fp16 m16n8k16 single product, 128x128 CTA tile, BK=64,
// 2-stage pipeline, 2 CTAs/SM. Dynamic smem: 2 x (A 16KB + B 16KB) = 64KB.
// SMEM row = 64 fp16 = 128 B, SW128-swizzled.
// MODE 1: A=[fb;fn] K=512 -> g_h.   MODE 2: A=[fb|h'|nf] K=1152 -> relu -> out.
// Warp grid 4(M) x 2(N); warp tile 32x64.
// ---------------------------------------------------------------------------
template <int MODE>
__global__ void __launch_bounds__(256, 2)
gemm_mma_kernel(const float* __restrict__ fb, const float* __restrict__ fn,
                const float* __restrict__ nf, float* __restrict__ outp)
{
    constexpr int KTOT   = (MODE == 1) ? F_DIM : KOUT;
    constexpr int NCHUNK = KTOT / 64;
    constexpr int MROWS  = (MODE == 1) ? NTOT : B_NODES;

    extern __shared__ char dsm[];
    const uint32_t ab = (smem_u32(dsm) + 1023u) & ~1023u;

    const int tid = threadIdx.x;
    const int lane = tid & 31;
    const int wm = (tid >> 5) & 3;       // 0..3  (M groups of 32 rows)
    const int wn = (tid >> 5) >> 2;      // 0..1  (N groups of 64 cols)
    const int rowBase = blockIdx.x * 128;

    const __half* BT = (MODE == 1) ? g_W16_1 : g_W16_2;

    float acc[2][8][4];
    #pragma unroll
    for (int i = 0; i < 2; ++i)
        #pragma unroll
        for (int j = 0; j < 8; ++j)
            #pragma unroll
            for (int q = 0; q < 4; ++q) acc[i][j][q] = 0.f;

    const int lr = lane & 7;
    const int lg = lane >> 3;

    // per-thread A staging: 4 segs x 8 floats (tile 128 rows x 64 fp16)
    float4 sa0[4], sa1[4];

    auto aSrc = [&](int grow, int k0c) -> const float* {
        if (MODE == 1) {
            return (grow < B_NODES) ? fb + (size_t)grow * F_DIM + k0c
                                    : fn + (size_t)(grow - B_NODES) * F_DIM + k0c;
        } else {
            if (k0c < 512)      return fb + (size_t)grow * F_DIM + k0c;
            else if (k0c < 640) return g_hprime + (size_t)grow * D_DIM + (k0c - 512);
            else                return nf + (size_t)grow * F_DIM + (k0c - 640);
        }
    };

    // Issue: LDG A (fp32) into regs; cp.async B (fp16) into stage smem.
    auto issueLoads = [&](int c, uint32_t stageB) {
        const int k0c = c * 64;
        #pragma unroll
        for (int i = 0; i < 4; ++i) {
            int idx = tid + i * 256;            // 0..1023
            int row = idx >> 3, seg = idx & 7;  // 128 rows x 8 segs of 8 els
            int grow = rowBase + row;
            sa0[i] = make_float4(0.f, 0.f, 0.f, 0.f);
            sa1[i] = sa0[i];
            if (grow < MROWS) {
                const float* src = aSrc(grow, k0c) + seg * 8;
                sa0[i] = *(const float4*)(src);
                sa1[i] = *(const float4*)(src + 4);
            }
        }
        #pragma unroll
        for (int i = 0; i < 4; ++i) {
            int idx = tid + i * 256;            // 0..1023
            int row = idx >> 3, seg = idx & 7;  // 128 n-rows x 8 segs of 16B
            uint32_t off = SMEM_SWIZZLE_128B((uint32_t)(row * 128 + seg * 16));
            cp_async16(stageB + off, BT + (size_t)row * KTOT + k0c + seg * 8);
        }
        CP_ASYNC_COMMIT();
    };

    // Commit: fp16-convert staged A, store to smem; drain B cp.async.
    auto commitLoads = [&](uint32_t stageA) {
        #pragma unroll
        for (int i = 0; i < 4; ++i) {
            int idx = tid + i * 256;
            int row = idx >> 3, seg = idx & 7;
            uint32_t w0 = pack_h2(sa0[i].x, sa0[i].y);
            uint32_t w1 = pack_h2(sa0[i].z, sa0[i].w);
            uint32_t w2 = pack_h2(sa1[i].x, sa1[i].y);
            uint32_t w3 = pack_h2(sa1[i].z, sa1[i].w);
            uint32_t off = SMEM_SWIZZLE_128B((uint32_t)(row * 128 + seg * 16));
            STS128(w0, w1, w2, w3, stageA + off);
        }
        CP_ASYNC_WAIT0();
    };

    // Compute one 64-wide chunk: 4 k16 steps.
    auto computeChunk = [&](uint32_t stageA, uint32_t stageB) {
        #pragma unroll
        for (int t = 0; t < 4; ++t) {
            uint32_t af[2][4];
            #pragma unroll
            for (int i = 0; i < 2; ++i) {
                int row = wm * 32 + i * 16 + lr + (lg & 1) * 8;
                int kb = t * 32 + (lg >> 1) * 16;
                ldm_x4(af[i], stageA + SMEM_SWIZZLE_128B((uint32_t)(row * 128 + kb)));
            }
            uint32_t bfr[4][4];
            #pragma unroll
            for (int j = 0; j < 4; ++j) {
                int row = wn * 64 + j * 16 + lr + (lg >> 1) * 8;
                int kb = t * 32 + (lg & 1) * 16;
                ldm_x4(bfr[j], stageB + SMEM_SWIZZLE_128B((uint32_t)(row * 128 + kb)));
            }
            #pragma unroll
            for (int i = 0; i < 2; ++i)
                #pragma unroll
                for (int j = 0; j < 4; ++j) {
                    mma_f16(acc[i][2 * j],     af[i], bfr[j][0], bfr[j][1]);
                    mma_f16(acc[i][2 * j + 1], af[i], bfr[j][2], bfr[j][3]);
                }
        }
    };

    auto stA = [&](int s) { return ab + (uint32_t)s * 32768u; };
    auto stB = [&](int s) { return ab + (uint32_t)s * 32768u + 16384u; };

    // ---- prologue ----
    issueLoads(0, stB(0));
    commitLoads(stA(0));
    __syncthreads();

    // ---- main pipeline ----
    for (int c = 0; c < NCHUNK; ++c) {
        const int cur = c & 1, nxt = (c + 1) & 1;
        if (c + 1 < NCHUNK) issueLoads(c + 1, stB(nxt));
        computeChunk(stA(cur), stB(cur));
        if (c + 1 < NCHUNK) commitLoads(stA(nxt));
        __syncthreads();
    }

    // ---- epilogue ----
    float* dst = (MODE == 1) ? (float*)g_h : outp;
    const int qm = lane >> 2;
    const int qn = (lane & 3) * 2;
    #pragma unroll
    for (int i = 0; i < 2; ++i) {
        #pragma unroll
        for (int j = 0; j < 8; ++j) {
            int m0 = rowBase + wm * 32 + i * 16;
            int n  = wn * 64 + j * 8 + qn;
            float c0 = acc[i][j][0], c1 = acc[i][j][1];
            float c2 = acc[i][j][2], c3 = acc[i][j][3];
            if (MODE == 2) {
                c0 = fmaxf(c0, 0.f); c1 = fmaxf(c1, 0.f);
                c2 = fmaxf(c2, 0.f); c3 = fmaxf(c3, 0.f);
            }
            int r0 = m0 + qm, r1 = m0 + 8 + qm;
            if (r0 < MROWS) *(float2*)(dst + (size_t)r0 * D_DIM + n) = make_float2(c0, c1);
            if (r1 < MROWS) *(float2*)(dst + (size_t)r1 * D_DIM + n) = make_float2(c2, c3);
        }
    }
}

// ---------------------------------------------------------------------------
// s[r] = g_h[r,:] . (a[0:128] if r<B else a[128:256])
// ---------------------------------------------------------------------------
__global__ void __launch_bounds__(256) s_kernel(const float* __restrict__ avec)
{
    int gwarp = (blockIdx.x * blockDim.x + threadIdx.x) >> 5;
    int lane = threadIdx.x & 31;
    if (gwarp >= NTOT) return;
    const float* av = (gwarp < B_NODES) ? avec : avec + D_DIM;
    const float* hr = g_h + (size_t)gwarp * D_DIM;
    float sum = 0.f;
    #pragma unroll
    for (int i = 0; i < 4; ++i) {
        int c = lane + i * 32;
        sum += hr[c] * av[c];
    }
    #pragma unroll
    for (int off = 16; off > 0; off >>= 1)
        sum += __shfl_down_sync(0xffffffffu, sum, off);
    if (lane == 0) g_s[gwarp] = sum;
}

// ---------------------------------------------------------------------------
// Aggregation: one block per batch node; thread t owns feature column t.
// ---------------------------------------------------------------------------
__global__ void __launch_bounds__(128) agg_kernel(const int* __restrict__ edge_dst)
{
    const int i = blockIdx.x;
    const int t = threadIdx.x;
    __shared__ float w[K_NEIGH];
    __shared__ int   jj[K_NEIGH];
    if (t < K_NEIGH) {
        int j = edge_dst[(size_t)i * K_NEIGH + t];
        float sc = g_s[i] + g_s[B_NODES + j];
        float lr = sc > 0.f ? sc : 0.2f * sc;
        w[t]  = expf(-lr);
        jj[t] = j;
    }
    __syncthreads();
    float tot = 0.f, acc = 0.f;
    #pragma unroll
    for (int k = 0; k < K_NEIGH; ++k) {
        float wk = w[k];
        tot += wk;
        acc += wk * g_h[(size_t)(B_NODES + jj[k]) * D_DIM + t];
    }
    float v = acc / tot;
    if (!isfinite(v)) v = 0.f;
    g_hprime[(size_t)i * D_DIM + t] = v;
}

// ---------------------------------------------------------------------------
// Launch
// Inputs: 0=feats_batch 1=feats_neigh 2=neigh_feats 3=W 4=a 5=Wd 6=edge_src 7=edge_dst
// ---------------------------------------------------------------------------
extern "C" void kernel_launch(void* const* d_in, const int* in_sizes, int n_in,
                              void* d_out, int out_size)
{
    const float* fb   = (const float*)d_in[0];
    const float* fn   = (const float*)d_in[1];
    const float* nf   = (const float*)d_in[2];
    const float* W    = (const float*)d_in[3];
    const float* avec = (const float*)d_in[4];
    const float* Wd   = (const float*)d_in[5];
    const int* edge_dst = (const int*)d_in[7];
    float* out = (float*)d_out;
    (void)in_sizes; (void)n_in; (void)out_size;

    const int SMEM_BYTES = 66560;  // 2 x 32KB stages + 1KB align slack
    cudaFuncSetAttribute(gemm_mma_kernel<1>, cudaFuncAttributeMaxDynamicSharedMemorySize, SMEM_BYTES);
    cudaFuncSetAttribute(gemm_mma_kernel<2>, cudaFuncAttributeMaxDynamicSharedMemorySize, SMEM_BYTES);

    // 0) fp16-round + transpose weights [N][K]
    convertW_kernel<1><<<(F_DIM * D_DIM + 255) / 256, 256>>>(W);
    convertW_kernel<2><<<(KOUT * D_DIM + 255) / 256, 256>>>(Wd);

    // 1) h = [fb; fn] @ W
    gemm_mma_kernel<1><<<(NTOT + 127) / 128, 256, SMEM_BYTES>>>(fb, fn, nullptr, nullptr);

    // 2) per-row attention scalars
    s_kernel<<<(NTOT * 32 + 255) / 256, 256>>>(avec);

    // 3) per-node weighted aggregation
    agg_kernel<<<B_NODES, 128>>>(edge_dst);

    // 4) out = relu([fb | h' | nf] @ Wd)
    gemm_mma_kernel<2><<<(B_NODES + 127) / 128, 256, SMEM_BYTES>>>(fb, nullptr, nf, out);
}

// round 10
// speedup vs baseline: 1.6528x; 1.0793x over previous
#include <cuda_runtime.h>
#include <cuda_fp16.h>
#include <cstdint>

// Problem constants
#define B_NODES 100000
#define U_NODES 50000
#define NTOT    150000
#define F_DIM   512
#define D_DIM   128
#define K_NEIGH 10
#define KOUT    1152

#define SMEM_SWIZZLE_128B(byte_offset) ((byte_offset) ^ (((byte_offset) >> 3) & 0x70))

// ---------------------------------------------------------------------------
// Warp-level tensor-core primitives
// ---------------------------------------------------------------------------
__device__ __forceinline__ uint32_t smem_u32(const void* p) {
    uint32_t a;
    asm("{ .reg .u64 t; cvta.to.shared.u64 t, %1; cvt.u32.u64 %0, t; }" : "=r"(a) : "l"(p));
    return a;
}

__device__ __forceinline__ void ldm_x4(uint32_t* r, uint32_t addr) {
    asm volatile("ldmatrix.sync.aligned.m8n8.x4.shared.b16 {%0,%1,%2,%3}, [%4];"
        : "=r"(r[0]), "=r"(r[1]), "=r"(r[2]), "=r"(r[3]) : "r"(addr));
}

__device__ __forceinline__ void mma_f16(float* c, const uint32_t* a,
                                        uint32_t b0, uint32_t b1) {
    asm volatile("mma.sync.aligned.m16n8k16.row.col.f32.f16.f16.f32 "
        "{%0,%1,%2,%3}, {%4,%5,%6,%7}, {%8,%9}, {%0,%1,%2,%3};"
        : "+f"(c[0]), "+f"(c[1]), "+f"(c[2]), "+f"(c[3])
        : "r"(a[0]), "r"(a[1]), "r"(a[2]), "r"(a[3]), "r"(b0), "r"(b1));
}

__device__ __forceinline__ uint32_t pack_h2(float x, float y) {
    __half2 h = __float22half2_rn(make_float2(x, y));
    return *reinterpret_cast<uint32_t*>(&h);
}

__device__ __forceinline__ void cp_async16(uint32_t dst, const void* src) {
    asm volatile("cp.async.cg.shared.global [%0], [%1], 16;" :: "r"(dst), "l"(src) : "memory");
}
#define CP_ASYNC_COMMIT() asm volatile("cp.async.commit_group;" ::: "memory")
#define CP_ASYNC_WAIT0()  asm volatile("cp.async.wait_group 0;" ::: "memory")

#define STS128(a0, a1, a2, a3, addr) \
    asm volatile("st.shared.v4.b32 [%0], {%1, %2, %3, %4};" \
        :: "r"(addr), "r"(a0), "r"(a1), "r"(a2), "r"(a3) : "memory")

// ---------------------------------------------------------------------------
// Device-global scratch (device-code references only)
// ---------------------------------------------------------------------------
__device__ float g_s[NTOT];
// fp16 h for NEIGHBOR rows only (rows B..B+U), [U][128]
__device__ __align__(16) __half g_h16[(size_t)U_NODES * D_DIM];
// fp16 h' [B][128], padded so OOB cp.async in the last CTA stays in-bounds
__device__ __align__(16) __half g_hprime16[(size_t)(B_NODES + 256) * D_DIM];
// fp16 transposed weights: [N=128][K]
__device__ __align__(16) __half g_W16_1[(size_t)D_DIM * F_DIM];
__device__ __align__(16) __half g_W16_2[(size_t)D_DIM * KOUT];

// ---------------------------------------------------------------------------
// Weight transpose + fp16 rounding: src [K][128] fp32 -> dstT [128][K] fp16
// ---------------------------------------------------------------------------
template <int WHICH>   // 1 = W (K=512), 2 = Wd (K=1152)
__global__ void convertW_kernel(const float* __restrict__ src)
{
    constexpr int K = (WHICH == 1) ? F_DIM : KOUT;
    __half* dstT = (WHICH == 1) ? g_W16_1 : g_W16_2;

    int idx = blockIdx.x * blockDim.x + threadIdx.x;
    if (idx >= K * D_DIM) return;
    int k = idx >> 7, n = idx & 127;
    dstT[(size_t)n * K + k] = __float2half_rn(src[idx]);
}

// Zero the fused-s accumulator (graph-replay safe: runs every launch)
__global__ void zero_s_kernel()
{
    int i = blockIdx.x * blockDim.x + threadIdx.x;
    if (i < NTOT) g_s[i] = 0.f;
}

// ---------------------------------------------------------------------------
// Tensor-core GEMM, fp16 m16n8k16, 128x128 CTA tile, BK=64, 2-stage pipeline,
// 2 CTAs/SM. Dynamic smem: 2 x (A 16KB + B 16KB) = 64KB.
// MODE 1: A=[fb;fn] K=512; FUSED epilogue: s += h.a_half (atomic), and
//         fp16 h written for neighbor rows only. No fp32 h output.
// MODE 2: A=[fb | h'16 | nf] K=1152 (h' chunks cp.async'd as fp16) -> relu out.
// Warp grid 4(M) x 2(N); warp tile 32x64.
// ---------------------------------------------------------------------------
template <int MODE>
__global__ void __launch_bounds__(256, 2)
gemm_mma_kernel(const float* __restrict__ fb, const float* __restrict__ fn,
                const float* __restrict__ nf, const float* __restrict__ avec,
                float* __restrict__ outp)
{
    constexpr int KTOT   = (MODE == 1) ? F_DIM : KOUT;
    constexpr int NCHUNK = KTOT / 64;
    constexpr int MROWS  = (MODE == 1) ? NTOT : B_NODES;

    extern __shared__ char dsm[];
    const uint32_t ab = (smem_u32(dsm) + 1023u) & ~1023u;

    const int tid = threadIdx.x;
    const int lane = tid & 31;
    const int wm = (tid >> 5) & 3;
    const int wn = (tid >> 5) >> 2;
    const int rowBase = blockIdx.x * 128;

    const __half* BT = (MODE == 1) ? g_W16_1 : g_W16_2;

    float acc[2][8][4];
    #pragma unroll
    for (int i = 0; i < 2; ++i)
        #pragma unroll
        for (int j = 0; j < 8; ++j)
            #pragma unroll
            for (int q = 0; q < 4; ++q) acc[i][j][q] = 0.f;

    const int lr = lane & 7;
    const int lg = lane >> 3;

    float4 sa0[4], sa1[4];

    // fp16-direct A chunk? (GEMM2's h' region, k in [512,640))
    auto isF16chunk = [&](int c) { return MODE == 2 && c >= 8 && c < 10; };

    auto aSrc = [&](int grow, int k0c) -> const float* {
        if (MODE == 1) {
            return (grow < B_NODES) ? fb + (size_t)grow * F_DIM + k0c
                                    : fn + (size_t)(grow - B_NODES) * F_DIM + k0c;
        } else {
            if (k0c < 512) return fb + (size_t)grow * F_DIM + k0c;
            else           return nf + (size_t)grow * F_DIM + (k0c - 640);
        }
    };

    // Issue: A via LDG->regs (fp32 chunks) or cp.async (fp16 h' chunks);
    //        B via cp.async.
    auto issueLoads = [&](int c, uint32_t stageA, uint32_t stageB) {
        const int k0c = c * 64;
        if (isF16chunk(c)) {
            // A tile already fp16 in g_hprime16 (padded: OOB rows safe)
            #pragma unroll
            for (int i = 0; i < 4; ++i) {
                int idx = tid + i * 256;
                int row = idx >> 3, seg = idx & 7;
                int grow = rowBase + row;   // may exceed B_NODES; pad covers it
                uint32_t off = SMEM_SWIZZLE_128B((uint32_t)(row * 128 + seg * 16));
                cp_async16(stageA + off,
                           g_hprime16 + (size_t)grow * D_DIM + (k0c - 512) + seg * 8);
            }
        } else {
            #pragma unroll
            for (int i = 0; i < 4; ++i) {
                int idx = tid + i * 256;
                int row = idx >> 3, seg = idx & 7;
                int grow = rowBase + row;
                sa0[i] = make_float4(0.f, 0.f, 0.f, 0.f);
                sa1[i] = sa0[i];
                if (grow < MROWS) {
                    const float* src = aSrc(grow, k0c) + seg * 8;
                    sa0[i] = *(const float4*)(src);
                    sa1[i] = *(const float4*)(src + 4);
                }
            }
        }
        #pragma unroll
        for (int i = 0; i < 4; ++i) {
            int idx = tid + i * 256;
            int row = idx >> 3, seg = idx & 7;
            uint32_t off = SMEM_SWIZZLE_128B((uint32_t)(row * 128 + seg * 16));
            cp_async16(stageB + off, BT + (size_t)row * KTOT + k0c + seg * 8);
        }
        CP_ASYNC_COMMIT();
    };

    auto commitLoads = [&](int c, uint32_t stageA) {
        if (!isF16chunk(c)) {
            #pragma unroll
            for (int i = 0; i < 4; ++i) {
                int idx = tid + i * 256;
                int row = idx >> 3, seg = idx & 7;
                uint32_t w0 = pack_h2(sa0[i].x, sa0[i].y);
                uint32_t w1 = pack_h2(sa0[i].z, sa0[i].w);
                uint32_t w2 = pack_h2(sa1[i].x, sa1[i].y);
                uint32_t w3 = pack_h2(sa1[i].z, sa1[i].w);
                uint32_t off = SMEM_SWIZZLE_128B((uint32_t)(row * 128 + seg * 16));
                STS128(w0, w1, w2, w3, stageA + off);
            }
        }
        CP_ASYNC_WAIT0();
    };

    auto computeChunk = [&](uint32_t stageA, uint32_t stageB) {
        #pragma unroll
        for (int t = 0; t < 4; ++t) {
            uint32_t af[2][4];
            #pragma unroll
            for (int i = 0; i < 2; ++i) {
                int row = wm * 32 + i * 16 + lr + (lg & 1) * 8;
                int kb = t * 32 + (lg >> 1) * 16;
                ldm_x4(af[i], stageA + SMEM_SWIZZLE_128B((uint32_t)(row * 128 + kb)));
            }
            uint32_t bfr[4][4];
            #pragma unroll
            for (int j = 0; j < 4; ++j) {
                int row = wn * 64 + j * 16 + lr + (lg >> 1) * 8;
                int kb = t * 32 + (lg & 1) * 16;
                ldm_x4(bfr[j], stageB + SMEM_SWIZZLE_128B((uint32_t)(row * 128 + kb)));
            }
            #pragma unroll
            for (int i = 0; i < 2; ++i)
                #pragma unroll
                for (int j = 0; j < 4; ++j) {
                    mma_f16(acc[i][2 * j],     af[i], bfr[j][0], bfr[j][1]);
                    mma_f16(acc[i][2 * j + 1], af[i], bfr[j][2], bfr[j][3]);
                }
        }
    };

    auto stA = [&](int s) { return ab + (uint32_t)s * 32768u; };
    auto stB = [&](int s) { return ab + (uint32_t)s * 32768u + 16384u; };

    issueLoads(0, stA(0), stB(0));
    commitLoads(0, stA(0));
    __syncthreads();

    for (int c = 0; c < NCHUNK; ++c) {
        const int cur = c & 1, nxt = (c + 1) & 1;
        if (c + 1 < NCHUNK) issueLoads(c + 1, stA(nxt), stB(nxt));
        computeChunk(stA(cur), stB(cur));
        if (c + 1 < NCHUNK) commitLoads(c + 1, stA(nxt));
        __syncthreads();
    }

    // ---- epilogue ----
    const int qm = lane >> 2;
    const int qn = (lane & 3) * 2;

    if (MODE == 1) {
        // Fused: s[r] += h[r,:].a_half(r); write fp16 h for neighbor rows.
        #pragma unroll
        for (int i = 0; i < 2; ++i) {
            int m0 = rowBase + wm * 32 + i * 16;
            int r0 = m0 + qm, r1 = m0 + 8 + qm;
            const float* av0 = (r0 < B_NODES) ? avec : avec + D_DIM;
            const float* av1 = (r1 < B_NODES) ? avec : avec + D_DIM;
            float s0 = 0.f, s1 = 0.f;
            #pragma unroll
            for (int j = 0; j < 8; ++j) {
                int n = wn * 64 + j * 8 + qn;
                float c0 = acc[i][j][0], c1 = acc[i][j][1];
                float c2 = acc[i][j][2], c3 = acc[i][j][3];
                s0 += c0 * av0[n] + c1 * av0[n + 1];
                s1 += c2 * av1[n] + c3 * av1[n + 1];
                if (r0 >= B_NODES && r0 < NTOT) {
                    __half2 h = __float22half2_rn(make_float2(c0, c1));
                    *(__half2*)(g_h16 + (size_t)(r0 - B_NODES) * D_DIM + n) = h;
                }
                if (r1 >= B_NODES && r1 < NTOT) {
                    __half2 h = __float22half2_rn(make_float2(c2, c3));
                    *(__half2*)(g_h16 + (size_t)(r1 - B_NODES) * D_DIM + n) = h;
                }
            }
            // quad reduction (lanes qn=0,2,4,6 share the same row)
            s0 += __shfl_xor_sync(0xffffffffu, s0, 1);
            s0 += __shfl_xor_sync(0xffffffffu, s0, 2);
            s1 += __shfl_xor_sync(0xffffffffu, s1, 1);
            s1 += __shfl_xor_sync(0xffffffffu, s1, 2);
            if ((lane & 3) == 0) {
                if (r0 < NTOT) atomicAdd(&g_s[r0], s0);
                if (r1 < NTOT) atomicAdd(&g_s[r1], s1);
            }
        }
    } else {
        #pragma unroll
        for (int i = 0; i < 2; ++i) {
            #pragma unroll
            for (int j = 0; j < 8; ++j) {
                int m0 = rowBase + wm * 32 + i * 16;
                int n  = wn * 64 + j * 8 + qn;
                float c0 = fmaxf(acc[i][j][0], 0.f), c1 = fmaxf(acc[i][j][1], 0.f);
                float c2 = fmaxf(acc[i][j][2], 0.f), c3 = fmaxf(acc[i][j][3], 0.f);
                int r0 = m0 + qm, r1 = m0 + 8 + qm;
                if (r0 < MROWS) *(float2*)(outp + (size_t)r0 * D_DIM + n) = make_float2(c0, c1);
                if (r1 < MROWS) *(float2*)(outp + (size_t)r1 * D_DIM + n) = make_float2(c2, c3);
            }
        }
    }
}

// ---------------------------------------------------------------------------
// Aggregation: one block per batch node; thread t owns feature column t.
// Reads fp16 h (neighbor rows), writes fp16 h'.
// ---------------------------------------------------------------------------
__global__ void __launch_bounds__(128) agg_kernel(const int* __restrict__ edge_dst)
{
    const int i = blockIdx.x;
    const int t = threadIdx.x;
    __shared__ float w[K_NEIGH];
    __shared__ int   jj[K_NEIGH];
    if (t < K_NEIGH) {
        int j = edge_dst[(size_t)i * K_NEIGH + t];
        float sc = g_s[i] + g_s[B_NODES + j];
        float lr = sc > 0.f ? sc : 0.2f * sc;   // leaky_relu, alpha=0.2
        w[t]  = expf(-lr);
        jj[t] = j;
    }
    __syncthreads();
    float tot = 0.f, acc = 0.f;
    #pragma unroll
    for (int k = 0; k < K_NEIGH; ++k) {
        float wk = w[k];
        tot += wk;
        acc += wk * __half2float(g_h16[(size_t)jj[k] * D_DIM + t]);
    }
    float v = acc / tot;
    if (!isfinite(v)) v = 0.f;   // nan_to_num guard
    g_hprime16[(size_t)i * D_DIM + t] = __float2half_rn(v);
}

// ---------------------------------------------------------------------------
// Launch
// Inputs: 0=feats_batch 1=feats_neigh 2=neigh_feats 3=W 4=a 5=Wd 6=edge_src 7=edge_dst
// ---------------------------------------------------------------------------
extern "C" void kernel_launch(void* const* d_in, const int* in_sizes, int n_in,
                              void* d_out, int out_size)
{
    const float* fb   = (const float*)d_in[0];
    const float* fn   = (const float*)d_in[1];
    const float* nf   = (const float*)d_in[2];
    const float* W    = (const float*)d_in[3];
    const float* avec = (const float*)d_in[4];
    const float* Wd   = (const float*)d_in[5];
    const int* edge_dst = (const int*)d_in[7];
    float* out = (float*)d_out;
    (void)in_sizes; (void)n_in; (void)out_size;

    const int SMEM_BYTES = 66560;  // 2 x 32KB stages + 1KB align slack
    cudaFuncSetAttribute(gemm_mma_kernel<1>, cudaFuncAttributeMaxDynamicSharedMemorySize, SMEM_BYTES);
    cudaFuncSetAttribute(gemm_mma_kernel<2>, cudaFuncAttributeMaxDynamicSharedMemorySize, SMEM_BYTES);

    // 0) fp16-round + transpose weights; zero fused-s accumulator
    convertW_kernel<1><<<(F_DIM * D_DIM + 255) / 256, 256>>>(W);
    convertW_kernel<2><<<(KOUT * D_DIM + 255) / 256, 256>>>(Wd);
    zero_s_kernel<<<(NTOT + 255) / 256, 256>>>();

    // 1) h = [fb; fn] @ W  (fused: s accumulation + fp16 neighbor-h write)
    gemm_mma_kernel<1><<<(NTOT + 127) / 128, 256, SMEM_BYTES>>>(fb, fn, nullptr, avec, nullptr);

    // 2) per-node weighted aggregation -> fp16 h'
    agg_kernel<<<B_NODES, 128>>>(edge_dst);

    // 3) out = relu([fb | h' | nf] @ Wd)
    gemm_mma_kernel<2><<<(B_NODES + 127) / 128, 256, SMEM_BYTES>>>(fb, nullptr, nf, nullptr, out);
}